// round 16
// baseline (speedup 1.0000x reference)
#include <cuda_runtime.h>
#include <cuda_fp16.h>
#include <cstdint>

#define Bv   8
#define Nv   4096
#define Dv   512
#define Gv   32
#define REDv 128
#define HIDv 129
#define Kv   4
#define ROWS (Bv*Nv)          // 32768

// ---------------- scratch (device globals; no allocation) ----------------
__device__ float  g_part[Bv*32*Dv];       // pooling partials
__device__ float  g_a[Bv*136];            // relu(fc1) activations
__device__ float  g_att[Bv*Kv];
__device__ float  g_bb[Bv*Dv];
__device__ __half g_Wbh[Bv*Dv*Dv];        // 4 MB per-sample kernels (fp16)
__device__ float  g_gate[ROWS*Gv];        // involution gates
__device__ __half g_xh[ROWS*Dv];          // fp16 copy of x (32 MB)
__device__ __half g_c1h[REDv*Dv];         // fp16 conv1_w
__device__ int    g_sync[ROWS/128];       // per-row-block completion counters (256)

// ---------------- helpers ----------------
__device__ __forceinline__ void mma_f16(float c[4], const uint32_t a[4], const uint32_t b[2]) {
    asm volatile(
        "mma.sync.aligned.m16n8k16.row.col.f32.f16.f16.f32 "
        "{%0,%1,%2,%3}, {%4,%5,%6,%7}, {%8,%9}, {%0,%1,%2,%3};\n"
        : "+f"(c[0]), "+f"(c[1]), "+f"(c[2]), "+f"(c[3])
        : "r"(a[0]), "r"(a[1]), "r"(a[2]), "r"(a[3]), "r"(b[0]), "r"(b[1]));
}

__device__ __forceinline__ void ldm4(uint32_t* r, uint32_t sa) {
    asm volatile("ldmatrix.sync.aligned.m8n8.x4.shared.b16 {%0,%1,%2,%3}, [%4];"
                 : "=r"(r[0]), "=r"(r[1]), "=r"(r[2]), "=r"(r[3]) : "r"(sa));
}

__device__ __forceinline__ void cp16s(unsigned sa, const void* gsrc) {
    asm volatile("cp.async.cg.shared.global [%0], [%1], 16;\n" :: "r"(sa), "l"(gsrc));
}
__device__ __forceinline__ void cp_commit() { asm volatile("cp.async.commit_group;\n" ::: "memory"); }
template<int N> __device__ __forceinline__ void cp_wait() { asm volatile("cp.async.wait_group %0;\n" :: "n"(N) : "memory"); }

__device__ __forceinline__ uint32_t smem_u32(const void* p) {
    return (uint32_t)__cvta_generic_to_shared(p);
}

// smem row stride (BK=64): 72 halves = 144 B = 9 granules (9r mod 8 = perm -> ldmatrix conflict-free)
#define RS64 72

// ---------------- 0) k_pre: pool partials + fp16 x + fp16 conv1_w + zero sync ctrs ----------------
__global__ __launch_bounds__(512) void k_pre(const float* __restrict__ x, const float* __restrict__ conv1_w) {
    __shared__ float4 sp[4][128];
    int b = blockIdx.x, chunk = blockIdx.y;      // grid (8, 32), block 512
    int t = threadIdx.x;
    int col = t & 127, rg = t >> 7;              // 4 row-groups x 32 rows

    if (t == 256) g_sync[b*32 + chunk] = 0;      // zero one counter per block

    size_t base = ((size_t)(b*Nv + chunk*128 + rg*32)) * Dv;
    const float4* xp = (const float4*)(x + base);
    __half2* xh = (__half2*)(g_xh + base);
    float4 acc = make_float4(0.f, 0.f, 0.f, 0.f);
#pragma unroll 4
    for (int r = 0; r < 32; r++) {
        float4 v = xp[r*(Dv/4) + col];
        acc.x += v.x; acc.y += v.y; acc.z += v.z; acc.w += v.w;
        xh[(r*(Dv/4) + col)*2]   = __floats2half2_rn(v.x, v.y);
        xh[(r*(Dv/4) + col)*2+1] = __floats2half2_rn(v.z, v.w);
    }
    sp[rg][col] = acc;
    __syncthreads();
    if (rg == 0) {
        float4 a0 = sp[0][col], a1 = sp[1][col], a2 = sp[2][col], a3 = sp[3][col];
        float4 s;   // fixed order: deterministic
        s.x = ((a0.x + a1.x) + a2.x) + a3.x;
        s.y = ((a0.y + a1.y) + a2.y) + a3.y;
        s.z = ((a0.z + a1.z) + a2.z) + a3.z;
        s.w = ((a0.w + a1.w) + a2.w) + a3.w;
        *(float4*)(g_part + ((size_t)(b*32 + chunk))*Dv + col*4) = s;
    }

    // conv1_w cvt: 16384 float4 over 256 blocks => 64 per block
    if (t < 64) {
        int i = (b*32 + chunk)*64 + t;
        float4 v = ((const float4*)conv1_w)[i];
        ((__half2*)g_c1h)[i*2]   = __floats2half2_rn(v.x, v.y);
        ((__half2*)g_c1h)[i*2+1] = __floats2half2_rn(v.z, v.w);
    }
}

// ---------------- 1) k_fc1: (redundant pool2) + fc1 + relu, 17 blocks ----------------
__global__ __launch_bounds__(256) void k_fc1(const float* __restrict__ fc1_w) {
    __shared__ float s_pool[Bv*Dv];    // 16 KB
    int t = threadIdx.x, warp = t >> 5, lane = t & 31;

    for (int idx = t; idx < Bv*Dv; idx += 256) {
        int b = idx >> 9, d = idx & 511;
        float s = 0.f;
#pragma unroll
        for (int c = 0; c < 32; c++) s += g_part[((size_t)(b*32 + c))*Dv + d];
        s_pool[idx] = s * (1.f / (float)Nv);
    }
    __syncthreads();

    int j = blockIdx.x*8 + warp;                  // grid 17, warp per hidden unit
    if (j < HIDv) {
        float w[16];
#pragma unroll
        for (int q = 0; q < 16; q++) w[q] = fc1_w[(size_t)j*Dv + lane + q*32];
#pragma unroll
        for (int b = 0; b < Bv; b++) {
            float s = 0.f;
#pragma unroll
            for (int q = 0; q < 16; q++) s += s_pool[b*Dv + lane + q*32] * w[q];
#pragma unroll
            for (int o = 16; o > 0; o >>= 1) s += __shfl_xor_sync(0xFFFFFFFFu, s, o);
            if (lane == 0) g_a[b*136 + j] = fmaxf(s, 0.f);
        }
    }
}

// ---------------- 2) k_att2: fc2 + softmax + bb (1 block) ----------------
__global__ __launch_bounds__(256) void k_att2(
    const float* __restrict__ fc2_w, const float* __restrict__ fc2_b,
    const float* __restrict__ dyn_b)
{
    __shared__ float lg_s[Bv][Kv];
    __shared__ float att_s[Bv][Kv];
    int w = threadIdx.x >> 5;                     // warp = batch
    int lane = threadIdx.x & 31;

    if (lane < Kv) {
        float s = fc2_b[lane];
        for (int j = 0; j < HIDv; j++) s += g_a[w*136 + j] * fc2_w[lane*HIDv + j];
        lg_s[w][lane] = s * (1.f/34.f);
    }
    __syncwarp();
    if (lane == 0) {
        float mx = -1e30f;
        for (int k = 0; k < Kv; k++) mx = fmaxf(mx, lg_s[w][k]);
        float den = 0.f, e[Kv];
        for (int k = 0; k < Kv; k++) { e[k] = expf(lg_s[w][k] - mx); den += e[k]; }
        for (int k = 0; k < Kv; k++) {
            float a = e[k] / den;
            att_s[w][k] = a;
            g_att[w*Kv + k] = a;
        }
    }
    __syncwarp();
    float a0 = att_s[w][0], a1 = att_s[w][1], a2 = att_s[w][2], a3 = att_s[w][3];
    for (int d = lane*4; d < Dv; d += 128) {
        float4 b0 = *(const float4*)(dyn_b + 0*Dv + d);
        float4 b1 = *(const float4*)(dyn_b + 1*Dv + d);
        float4 b2 = *(const float4*)(dyn_b + 2*Dv + d);
        float4 b3 = *(const float4*)(dyn_b + 3*Dv + d);
        float4 r;
        r.x = a0*b0.x + a1*b1.x + a2*b2.x + a3*b3.x;
        r.y = a0*b0.y + a1*b1.y + a2*b2.y + a3*b3.y;
        r.z = a0*b0.z + a1*b1.z + a2*b2.z + a3*b3.z;
        r.w = a0*b0.w + a1*b1.w + a2*b2.w + a3*b3.w;
        *(float4*)(g_bb + w*Dv + d) = r;
    }
}

// ---------------- 3) k_gate: conv1 GEMM (BM=128,BK=64) + BN/relu + conv2 + Wb ----------------
// 8 warps 2x4, warp tile 64x32. 3-stage cp.async ring, lookahead 2. Grid 256 blocks.
__global__ __launch_bounds__(256) void k_gate(
    const float* __restrict__ bn_g, const float* __restrict__ bn_b,
    const float* __restrict__ bn_m, const float* __restrict__ bn_v,
    const float* __restrict__ conv2_w, const float* __restrict__ conv2_b,
    const float* __restrict__ dyn_w)
{
    extern __shared__ __align__(16) unsigned char dsm[];
    uint32_t sbase = (smem_u32(dsm) + 127u) & ~127u;
    const uint32_t PSA = 128*RS64*2;              // 18432 B
    const uint32_t PS  = 2*PSA;                   // 36864 B

    int row0 = blockIdx.x * 128;
    int t = threadIdx.x, warp = t >> 5, lane = t & 31;
    int g8 = lane >> 2, t4 = lane & 3;
    int wm = warp >> 2, wn = warp & 3;

    float acc[4][4][4];
#pragma unroll
    for (int mi = 0; mi < 4; mi++)
#pragma unroll
        for (int ni = 0; ni < 4; ni++)
#pragma unroll
            for (int q = 0; q < 4; q++) acc[mi][ni][q] = 0.f;

    auto issue = [&](int kt, int s) {
        uint32_t ab = sbase + s*PS;
        uint32_t bbuf = ab + PSA;
        int k0 = kt * 64;
#pragma unroll
        for (int i = 0; i < 4; i++) {
            int lin = t + i*256, r = lin >> 3, ch = lin & 7;
            uint32_t off = (uint32_t)(r*144 + ch*16);
            cp16s(ab   + off, g_xh  + ((size_t)(row0 + r))*Dv + k0 + ch*8);
            cp16s(bbuf + off, g_c1h + (size_t)r*Dv + k0 + ch*8);
        }
        cp_commit();
    };

    auto ldfragsA = [&](uint32_t ab, int cb, uint32_t af[4][4]) {
#pragma unroll
        for (int mi = 0; mi < 4; mi++) {
            int rm = wm*64 + mi*16;
            int row = rm + ((lane>>3)&1)*8 + (lane&7);
            int gr  = cb + (lane>>4);
            ldm4(af[mi], ab + (uint32_t)(row*144 + gr*16));
        }
    };
    auto ldfragsB = [&](uint32_t bbuf, int cb, uint32_t bq[2][4]) {
#pragma unroll
        for (int p = 0; p < 2; p++) {
            int cn = wn*32 + p*16;
            int row = cn + (lane>>4)*8 + (lane&7);
            int gr  = cb + ((lane>>3)&1);
            ldm4(bq[p], bbuf + (uint32_t)(row*144 + gr*16));
        }
    };

    auto mma_step = [&](uint32_t af[4][4], uint32_t bq[2][4]) {
#pragma unroll
        for (int mi = 0; mi < 4; mi++)
#pragma unroll
            for (int ni = 0; ni < 4; ni++) {
                uint32_t bf[2] = { bq[ni>>1][(ni&1)*2], bq[ni>>1][(ni&1)*2+1] };
                mma_f16(acc[mi][ni], af[mi], bf);
            }
    };

    issue(0, 0); issue(1, 1);
    for (int kt = 0; kt < 8; kt++) {
        if (kt < 7) cp_wait<1>(); else cp_wait<0>();
        __syncthreads();
        if (kt + 2 < 8) issue(kt + 2, (kt + 2) % 3);

        uint32_t ab = sbase + (kt % 3)*PS;
        uint32_t bbuf = ab + PSA;

        uint32_t afA[4][4], afB[4][4], bqA[2][4], bqB[2][4];
        ldfragsA(ab, 0, afA);  ldfragsB(bbuf, 0, bqA);
        ldfragsA(ab, 2, afB);  ldfragsB(bbuf, 2, bqB);
        mma_step(afA, bqA);
        mma_step(afB, bqB);
        ldfragsA(ab, 4, afA);  ldfragsB(bbuf, 4, bqA);
        ldfragsA(ab, 6, afB);  ldfragsB(bbuf, 6, bqB);
        mma_step(afA, bqA);
        mma_step(afB, bqB);
    }
    __syncthreads();

    // epilogue buffers: hbuf [128][132] floats (67584 B), wT [128][32] floats (16384 B)
    float* hbuf = (float*)dsm;
    float* wT = (float*)(dsm + 67840);

    for (int l = t; l < REDv*Gv; l += 256) {
        int j = l >> 5, g = l & 31;
        wT[l] = conv2_w[g*REDv + j];
    }

#pragma unroll
    for (int mi = 0; mi < 4; mi++) {
#pragma unroll
        for (int ni = 0; ni < 4; ni++) {
            int c0 = wn*32 + ni*8 + t4*2;
#pragma unroll
            for (int half = 0; half < 2; half++) {
                int c = c0 + half;
                float sc = bn_g[c] * rsqrtf(bn_v[c] + 1e-5f);
                float sh = bn_b[c] - bn_m[c]*sc;
                int rr = wm*64 + mi*16 + g8;
                hbuf[rr*132 + c]     = fmaxf(acc[mi][ni][half]     * sc + sh, 0.f);
                hbuf[(rr+8)*132 + c] = fmaxf(acc[mi][ni][2 + half] * sc + sh, 0.f);
            }
        }
    }
    __syncthreads();

    // gate[r,g] = conv2_b[g] + sum_j h[r][j]*wT[j][g]  (float4 hbuf reads)
    {
        int g = t & 31;
        int rbase = t >> 5;
        float s[16];
        float cb2 = conv2_b[g];
#pragma unroll
        for (int i = 0; i < 16; i++) s[i] = cb2;
#pragma unroll 4
        for (int j4 = 0; j4 < REDv/4; j4++) {
            float wv0 = wT[(j4*4+0)*32 + g];
            float wv1 = wT[(j4*4+1)*32 + g];
            float wv2 = wT[(j4*4+2)*32 + g];
            float wv3 = wT[(j4*4+3)*32 + g];
#pragma unroll
            for (int i = 0; i < 16; i++) {
                int r = rbase + i*8;
                float4 h4 = *(const float4*)(hbuf + r*132 + j4*4);
                s[i] += h4.x*wv0 + h4.y*wv1 + h4.z*wv2 + h4.w*wv3;
            }
        }
#pragma unroll
        for (int i = 0; i < 16; i++) {
            int r = rbase + i*8;
            g_gate[((size_t)(row0 + r))*Gv + g] = s[i];
        }
    }

    // folded Wb build: 2048 float4 per block (grid 256)
#pragma unroll
    for (int i = 0; i < 8; i++) {
        int idx = blockIdx.x*2048 + i*256 + t;
        int b = idx >> 16;
        float at0 = g_att[b*4+0], at1 = g_att[b*4+1], at2 = g_att[b*4+2], at3 = g_att[b*4+3];
        int r = idx & 65535;
        const float4* w4 = (const float4*)dyn_w;
        float4 v0 = w4[0*65536 + r], v1 = w4[1*65536 + r], v2 = w4[2*65536 + r], v3 = w4[3*65536 + r];
        float ox = at0*v0.x + at1*v1.x + at2*v2.x + at3*v3.x;
        float oy = at0*v0.y + at1*v1.y + at2*v2.y + at3*v3.y;
        float oz = at0*v0.z + at1*v1.z + at2*v2.z + at3*v3.z;
        float ow = at0*v0.w + at1*v1.w + at2*v2.w + at3*v3.w;
        ((__half2*)g_Wbh)[idx*2]   = __floats2half2_rn(ox, oy);
        ((__half2*)g_Wbh)[idx*2+1] = __floats2half2_rn(oz, ow);
    }
}

// ---------------- 4) k_gemm: out2 GEMM + fused epilogue + counter-gated LN ----------------
// Grid (4, 256), BM=128, BN=128, BK=64, 3-stage/lookahead-2 (R11 mainloop unchanged).
// After epilogue: threadfence + atomicAdd on row-block counter; last CTA (old==3)
// runs LN+residual for the 128 rows (y is L2-resident: 64 MB out fits 126 MB L2).
__global__ __launch_bounds__(256, 2) void k_gemm(
    const float* __restrict__ x, const float* __restrict__ ln_g,
    const float* __restrict__ ln_b, float* __restrict__ out)
{
    extern __shared__ __align__(16) unsigned char dsm[];
    __shared__ int s_old;
    uint32_t sbase = (smem_u32(dsm) + 127u) & ~127u;
    const uint32_t PSA = 128*RS64*2;              // 18432 B
    const uint32_t PS  = 2*PSA;                   // 36864 B

    int col0 = blockIdx.x * 128;
    int row0 = blockIdx.y * 128;
    int b = row0 >> 12;
    const __half* Bp = g_Wbh + (size_t)b*Dv*Dv;

    int t = threadIdx.x, warp = t >> 5, lane = t & 31;
    int g8 = lane >> 2, t4 = lane & 3;
    int wm = warp >> 2, wn = warp & 3;

    float acc[4][4][4];
#pragma unroll
    for (int mi = 0; mi < 4; mi++)
#pragma unroll
        for (int ni = 0; ni < 4; ni++)
#pragma unroll
            for (int q = 0; q < 4; q++) acc[mi][ni][q] = 0.f;

    auto issue = [&](int kt, int s) {
        uint32_t ab = sbase + s*PS;
        uint32_t bbuf = ab + PSA;
        int k0 = kt * 64;
#pragma unroll
        for (int i = 0; i < 4; i++) {
            int lin = t + i*256, r = lin >> 3, ch = lin & 7;
            uint32_t off = (uint32_t)(r*144 + ch*16);
            cp16s(ab   + off, g_xh + ((size_t)(row0 + r))*Dv + k0 + ch*8);
            cp16s(bbuf + off, Bp   + ((size_t)(col0 + r))*Dv + k0 + ch*8);
        }
        cp_commit();
    };

    auto ldfragsA = [&](uint32_t ab, int cb, uint32_t af[4][4]) {
#pragma unroll
        for (int mi = 0; mi < 4; mi++) {
            int rm = wm*64 + mi*16;
            int row = rm + ((lane>>3)&1)*8 + (lane&7);
            int gr  = cb + (lane>>4);
            ldm4(af[mi], ab + (uint32_t)(row*144 + gr*16));
        }
    };
    auto ldfragsB = [&](uint32_t bbuf, int cb, uint32_t bq[2][4]) {
#pragma unroll
        for (int p = 0; p < 2; p++) {
            int cn = wn*32 + p*16;
            int row = cn + (lane>>4)*8 + (lane&7);
            int gr  = cb + ((lane>>3)&1);
            ldm4(bq[p], bbuf + (uint32_t)(row*144 + gr*16));
        }
    };

    auto mma_step = [&](uint32_t af[4][4], uint32_t bq[2][4]) {
#pragma unroll
        for (int mi = 0; mi < 4; mi++)
#pragma unroll
            for (int ni = 0; ni < 4; ni++) {
                uint32_t bf[2] = { bq[ni>>1][(ni&1)*2], bq[ni>>1][(ni&1)*2+1] };
                mma_f16(acc[mi][ni], af[mi], bf);
            }
    };

    issue(0, 0); issue(1, 1);
    for (int kt = 0; kt < 8; kt++) {
        if (kt < 7) cp_wait<1>(); else cp_wait<0>();
        __syncthreads();
        if (kt + 2 < 8) issue(kt + 2, (kt + 2) % 3);   // never aliases kt%3

        uint32_t ab = sbase + (kt % 3)*PS;
        uint32_t bbuf = ab + PSA;

        uint32_t afA[4][4], afB[4][4], bqA[2][4], bqB[2][4];
        ldfragsA(ab, 0, afA);  ldfragsB(bbuf, 0, bqA);
        ldfragsA(ab, 2, afB);  ldfragsB(bbuf, 2, bqB);
        mma_step(afA, bqA);
        mma_step(afB, bqB);
        ldfragsA(ab, 4, afA);  ldfragsB(bbuf, 4, bqA);
        ldfragsA(ab, 6, afB);  ldfragsB(bbuf, 6, bqB);
        mma_step(afA, bqA);
        mma_step(afB, bqB);
    }

    // epilogue: y = acc + bb[b,c] + x*gate
#pragma unroll
    for (int mi = 0; mi < 4; mi++) {
        int R0 = row0 + wm*64 + mi*16 + g8;
#pragma unroll
        for (int ni = 0; ni < 4; ni++) {
            int c = col0 + wn*32 + ni*8 + t4*2;
            float bb0 = g_bb[b*Dv + c], bb1 = g_bb[b*Dv + c + 1];
            int grp = c >> 4;

            float gv0 = g_gate[((size_t)R0)*Gv + grp];
            float2 xv0 = *(const float2*)(x + ((size_t)R0)*Dv + c);
            float2 y0;
            y0.x = acc[mi][ni][0] + bb0 + xv0.x*gv0;
            y0.y = acc[mi][ni][1] + bb1 + xv0.y*gv0;
            *(float2*)(out + ((size_t)R0)*Dv + c) = y0;

            int R1 = R0 + 8;
            float gv1 = g_gate[((size_t)R1)*Gv + grp];
            float2 xv1 = *(const float2*)(x + ((size_t)R1)*Dv + c);
            float2 y1;
            y1.x = acc[mi][ni][2] + bb0 + xv1.x*gv1;
            y1.y = acc[mi][ni][3] + bb1 + xv1.y*gv1;
            *(float2*)(out + ((size_t)R1)*Dv + c) = y1;
        }
    }

    // ---- completion counter: last of the 4 col-tile CTAs runs LN for this row-block ----
    __threadfence();                       // make this CTA's y writes visible device-wide
    __syncthreads();                       // all threads' writes fenced before the atomic
    if (t == 0) s_old = atomicAdd(&g_sync[blockIdx.y], 1);
    __syncthreads();
    if (s_old == 3) {
        __threadfence();                   // order counter read before y reads (acquire)
        for (int i = 0; i < 16; i++) {
            int R = row0 + warp*16 + i;
            const float4* y4 = (const float4*)(out + (size_t)R*Dv);
            float4 v[4];
            float s = 0.f, s2 = 0.f;
#pragma unroll
            for (int j = 0; j < 4; j++) {
                v[j] = y4[lane + 32*j];
                s  += v[j].x + v[j].y + v[j].z + v[j].w;
                s2 += v[j].x*v[j].x + v[j].y*v[j].y + v[j].z*v[j].z + v[j].w*v[j].w;
            }
#pragma unroll
            for (int o = 16; o > 0; o >>= 1) {
                s  += __shfl_xor_sync(0xFFFFFFFFu, s, o);
                s2 += __shfl_xor_sync(0xFFFFFFFFu, s2, o);
            }
            float mu = s * (1.f/Dv);
            float var = s2 * (1.f/Dv) - mu*mu;
            float rs = rsqrtf(var + 1e-5f);

            const float4* x4 = (const float4*)(x + (size_t)R*Dv);
            const float4* g4 = (const float4*)ln_g;
            const float4* b4 = (const float4*)ln_b;
            float4* o4 = (float4*)(out + (size_t)R*Dv);
#pragma unroll
            for (int j = 0; j < 4; j++) {
                int q = lane + 32*j;
                float4 gg = g4[q], bbv = b4[q], xx = x4[q];
                float4 o;
                o.x = (v[j].x - mu)*rs*gg.x + bbv.x + xx.x;
                o.y = (v[j].y - mu)*rs*gg.y + bbv.y + xx.y;
                o.z = (v[j].z - mu)*rs*gg.z + bbv.z + xx.z;
                o.w = (v[j].w - mu)*rs*gg.w + bbv.w + xx.w;
                o4[q] = o;
            }
        }
    }
}

// ---------------- launch ----------------
extern "C" void kernel_launch(void* const* d_in, const int* in_sizes, int n_in,
                              void* d_out, int out_size) {
    const float* x       = (const float*)d_in[0];
    const float* conv1_w = (const float*)d_in[1];
    const float* bn_g    = (const float*)d_in[2];
    const float* bn_b    = (const float*)d_in[3];
    const float* bn_m    = (const float*)d_in[4];
    const float* bn_v    = (const float*)d_in[5];
    const float* conv2_w = (const float*)d_in[6];
    const float* conv2_b = (const float*)d_in[7];
    const float* fc1_w   = (const float*)d_in[8];
    const float* fc2_w   = (const float*)d_in[9];
    const float* fc2_b   = (const float*)d_in[10];
    const float* dyn_w   = (const float*)d_in[11];
    const float* dyn_b   = (const float*)d_in[12];
    const float* ln_g    = (const float*)d_in[13];
    const float* ln_b    = (const float*)d_in[14];
    float* out = (float*)d_out;

    const int SM_PIPE = 3*2*128*RS64*2 + 128;        // 110720 B (3 stages x 36864)
    cudaFuncSetAttribute(k_gate, cudaFuncAttributeMaxDynamicSharedMemorySize, SM_PIPE);
    cudaFuncSetAttribute(k_gemm, cudaFuncAttributeMaxDynamicSharedMemorySize, SM_PIPE);

    k_pre <<<dim3(Bv, 32), 512>>>(x, conv1_w);
    k_fc1 <<<17, 256>>>(fc1_w);
    k_att2<<<1, 256>>>(fc2_w, fc2_b, dyn_b);
    k_gate<<<ROWS/128, 256, SM_PIPE>>>(bn_g, bn_b, bn_m, bn_v,
                                       conv2_w, conv2_b, dyn_w);
    k_gemm<<<dim3(Dv/128, ROWS/128), 256, SM_PIPE>>>(x, ln_g, ln_b, out);
}

// round 17
// speedup vs baseline: 1.0397x; 1.0397x over previous
#include <cuda_runtime.h>
#include <cuda_fp16.h>
#include <cstdint>

#define Bv   8
#define Nv   4096
#define Dv   512
#define Gv   32
#define REDv 128
#define HIDv 129
#define Kv   4
#define ROWS (Bv*Nv)          // 32768

// ---------------- scratch (device globals; no allocation) ----------------
__device__ float  g_part[Bv*32*Dv];       // pooling partials
__device__ float  g_a[Bv*136];            // relu(fc1) activations
__device__ float  g_att[Bv*Kv];
__device__ float  g_bb[Bv*Dv];
__device__ __half g_Wbh[Bv*Dv*Dv];        // 4 MB per-sample kernels (fp16)
__device__ float  g_gate[ROWS*Gv];        // involution gates
__device__ __half g_xh[ROWS*Dv];          // fp16 copy of x (32 MB)
__device__ __half g_c1h[REDv*Dv];         // fp16 conv1_w

// ---------------- helpers ----------------
__device__ __forceinline__ void mma_f16(float c[4], const uint32_t a[4], const uint32_t b[2]) {
    asm volatile(
        "mma.sync.aligned.m16n8k16.row.col.f32.f16.f16.f32 "
        "{%0,%1,%2,%3}, {%4,%5,%6,%7}, {%8,%9}, {%0,%1,%2,%3};\n"
        : "+f"(c[0]), "+f"(c[1]), "+f"(c[2]), "+f"(c[3])
        : "r"(a[0]), "r"(a[1]), "r"(a[2]), "r"(a[3]), "r"(b[0]), "r"(b[1]));
}

__device__ __forceinline__ void ldm4(uint32_t* r, uint32_t sa) {
    asm volatile("ldmatrix.sync.aligned.m8n8.x4.shared.b16 {%0,%1,%2,%3}, [%4];"
                 : "=r"(r[0]), "=r"(r[1]), "=r"(r[2]), "=r"(r[3]) : "r"(sa));
}

__device__ __forceinline__ void cp16s(unsigned sa, const void* gsrc) {
    asm volatile("cp.async.cg.shared.global [%0], [%1], 16;\n" :: "r"(sa), "l"(gsrc));
}
__device__ __forceinline__ void cp_commit() { asm volatile("cp.async.commit_group;\n" ::: "memory"); }
template<int N> __device__ __forceinline__ void cp_wait() { asm volatile("cp.async.wait_group %0;\n" :: "n"(N) : "memory"); }

__device__ __forceinline__ uint32_t smem_u32(const void* p) {
    return (uint32_t)__cvta_generic_to_shared(p);
}

// smem row stride (BK=64): 72 halves = 144 B = 9 granules (9r mod 8 = perm -> ldmatrix conflict-free)
#define RS64 72

// ---------------- 0) k_pre: pool partials + fp16 x + fp16 conv1_w (512 thr) ----------------
__global__ __launch_bounds__(512) void k_pre(const float* __restrict__ x, const float* __restrict__ conv1_w) {
    __shared__ float4 sp[4][128];
    int b = blockIdx.x, chunk = blockIdx.y;      // grid (8, 32), block 512
    int t = threadIdx.x;
    int col = t & 127, rg = t >> 7;              // 4 row-groups x 32 rows

    size_t base = ((size_t)(b*Nv + chunk*128 + rg*32)) * Dv;
    const float4* xp = (const float4*)(x + base);
    __half2* xh = (__half2*)(g_xh + base);
    float4 acc = make_float4(0.f, 0.f, 0.f, 0.f);
#pragma unroll 4
    for (int r = 0; r < 32; r++) {
        float4 v = xp[r*(Dv/4) + col];
        acc.x += v.x; acc.y += v.y; acc.z += v.z; acc.w += v.w;
        xh[(r*(Dv/4) + col)*2]   = __floats2half2_rn(v.x, v.y);
        xh[(r*(Dv/4) + col)*2+1] = __floats2half2_rn(v.z, v.w);
    }
    sp[rg][col] = acc;
    __syncthreads();
    if (rg == 0) {
        float4 a0 = sp[0][col], a1 = sp[1][col], a2 = sp[2][col], a3 = sp[3][col];
        float4 s;   // fixed order: deterministic
        s.x = ((a0.x + a1.x) + a2.x) + a3.x;
        s.y = ((a0.y + a1.y) + a2.y) + a3.y;
        s.z = ((a0.z + a1.z) + a2.z) + a3.z;
        s.w = ((a0.w + a1.w) + a2.w) + a3.w;
        *(float4*)(g_part + ((size_t)(b*32 + chunk))*Dv + col*4) = s;
    }

    // conv1_w cvt: 16384 float4 over 256 blocks => 64 per block
    if (t < 64) {
        int i = (b*32 + chunk)*64 + t;
        float4 v = ((const float4*)conv1_w)[i];
        ((__half2*)g_c1h)[i*2]   = __floats2half2_rn(v.x, v.y);
        ((__half2*)g_c1h)[i*2+1] = __floats2half2_rn(v.z, v.w);
    }
}

// ---------------- 1) k_fc1: (redundant pool2) + fc1 + relu, 17 blocks ----------------
__global__ __launch_bounds__(256) void k_fc1(const float* __restrict__ fc1_w) {
    __shared__ float s_pool[Bv*Dv];    // 16 KB
    int t = threadIdx.x, warp = t >> 5, lane = t & 31;

    for (int idx = t; idx < Bv*Dv; idx += 256) {
        int b = idx >> 9, d = idx & 511;
        float s = 0.f;
#pragma unroll
        for (int c = 0; c < 32; c++) s += g_part[((size_t)(b*32 + c))*Dv + d];
        s_pool[idx] = s * (1.f / (float)Nv);
    }
    __syncthreads();

    int j = blockIdx.x*8 + warp;                  // grid 17, warp per hidden unit
    if (j < HIDv) {
        float w[16];
#pragma unroll
        for (int q = 0; q < 16; q++) w[q] = fc1_w[(size_t)j*Dv + lane + q*32];
#pragma unroll
        for (int b = 0; b < Bv; b++) {
            float s = 0.f;
#pragma unroll
            for (int q = 0; q < 16; q++) s += s_pool[b*Dv + lane + q*32] * w[q];
#pragma unroll
            for (int o = 16; o > 0; o >>= 1) s += __shfl_xor_sync(0xFFFFFFFFu, s, o);
            if (lane == 0) g_a[b*136 + j] = fmaxf(s, 0.f);
        }
    }
}

// ---------------- 2) k_att2: fc2 + softmax + bb (1 block) ----------------
__global__ __launch_bounds__(256) void k_att2(
    const float* __restrict__ fc2_w, const float* __restrict__ fc2_b,
    const float* __restrict__ dyn_b)
{
    __shared__ float lg_s[Bv][Kv];
    __shared__ float att_s[Bv][Kv];
    int w = threadIdx.x >> 5;                     // warp = batch
    int lane = threadIdx.x & 31;

    if (lane < Kv) {
        float s = fc2_b[lane];
        for (int j = 0; j < HIDv; j++) s += g_a[w*136 + j] * fc2_w[lane*HIDv + j];
        lg_s[w][lane] = s * (1.f/34.f);
    }
    __syncwarp();
    if (lane == 0) {
        float mx = -1e30f;
        for (int k = 0; k < Kv; k++) mx = fmaxf(mx, lg_s[w][k]);
        float den = 0.f, e[Kv];
        for (int k = 0; k < Kv; k++) { e[k] = expf(lg_s[w][k] - mx); den += e[k]; }
        for (int k = 0; k < Kv; k++) {
            float a = e[k] / den;
            att_s[w][k] = a;
            g_att[w*Kv + k] = a;
        }
    }
    __syncwarp();
    float a0 = att_s[w][0], a1 = att_s[w][1], a2 = att_s[w][2], a3 = att_s[w][3];
    for (int d = lane*4; d < Dv; d += 128) {
        float4 b0 = *(const float4*)(dyn_b + 0*Dv + d);
        float4 b1 = *(const float4*)(dyn_b + 1*Dv + d);
        float4 b2 = *(const float4*)(dyn_b + 2*Dv + d);
        float4 b3 = *(const float4*)(dyn_b + 3*Dv + d);
        float4 r;
        r.x = a0*b0.x + a1*b1.x + a2*b2.x + a3*b3.x;
        r.y = a0*b0.y + a1*b1.y + a2*b2.y + a3*b3.y;
        r.z = a0*b0.z + a1*b1.z + a2*b2.z + a3*b3.z;
        r.w = a0*b0.w + a1*b1.w + a2*b2.w + a3*b3.w;
        *(float4*)(g_bb + w*Dv + d) = r;
    }
}

// ---------------- 3) k_gate: conv1 GEMM (BM=128,BK=64) + BN/relu + conv2 + Wb ----------------
// 8 warps 2x4, warp tile 64x32. 3-stage cp.async ring, lookahead 2. Grid 256 blocks.
__global__ __launch_bounds__(256) void k_gate(
    const float* __restrict__ bn_g, const float* __restrict__ bn_b,
    const float* __restrict__ bn_m, const float* __restrict__ bn_v,
    const float* __restrict__ conv2_w, const float* __restrict__ conv2_b,
    const float* __restrict__ dyn_w)
{
    extern __shared__ __align__(16) unsigned char dsm[];
    uint32_t sbase = (smem_u32(dsm) + 127u) & ~127u;
    const uint32_t PSA = 128*RS64*2;              // 18432 B
    const uint32_t PS  = 2*PSA;                   // 36864 B

    int row0 = blockIdx.x * 128;
    int t = threadIdx.x, warp = t >> 5, lane = t & 31;
    int g8 = lane >> 2, t4 = lane & 3;
    int wm = warp >> 2, wn = warp & 3;

    float acc[4][4][4];
#pragma unroll
    for (int mi = 0; mi < 4; mi++)
#pragma unroll
        for (int ni = 0; ni < 4; ni++)
#pragma unroll
            for (int q = 0; q < 4; q++) acc[mi][ni][q] = 0.f;

    auto issue = [&](int kt, int s) {
        uint32_t ab = sbase + s*PS;
        uint32_t bbuf = ab + PSA;
        int k0 = kt * 64;
#pragma unroll
        for (int i = 0; i < 4; i++) {
            int lin = t + i*256, r = lin >> 3, ch = lin & 7;
            uint32_t off = (uint32_t)(r*144 + ch*16);
            cp16s(ab   + off, g_xh  + ((size_t)(row0 + r))*Dv + k0 + ch*8);
            cp16s(bbuf + off, g_c1h + (size_t)r*Dv + k0 + ch*8);
        }
        cp_commit();
    };

    auto ldfragsA = [&](uint32_t ab, int cb, uint32_t af[4][4]) {
#pragma unroll
        for (int mi = 0; mi < 4; mi++) {
            int rm = wm*64 + mi*16;
            int row = rm + ((lane>>3)&1)*8 + (lane&7);
            int gr  = cb + (lane>>4);
            ldm4(af[mi], ab + (uint32_t)(row*144 + gr*16));
        }
    };
    auto ldfragsB = [&](uint32_t bbuf, int cb, uint32_t bq[2][4]) {
#pragma unroll
        for (int p = 0; p < 2; p++) {
            int cn = wn*32 + p*16;
            int row = cn + (lane>>4)*8 + (lane&7);
            int gr  = cb + ((lane>>3)&1);
            ldm4(bq[p], bbuf + (uint32_t)(row*144 + gr*16));
        }
    };

    auto mma_step = [&](uint32_t af[4][4], uint32_t bq[2][4]) {
#pragma unroll
        for (int mi = 0; mi < 4; mi++)
#pragma unroll
            for (int ni = 0; ni < 4; ni++) {
                uint32_t bf[2] = { bq[ni>>1][(ni&1)*2], bq[ni>>1][(ni&1)*2+1] };
                mma_f16(acc[mi][ni], af[mi], bf);
            }
    };

    issue(0, 0); issue(1, 1);
    for (int kt = 0; kt < 8; kt++) {
        if (kt < 7) cp_wait<1>(); else cp_wait<0>();
        __syncthreads();
        if (kt + 2 < 8) issue(kt + 2, (kt + 2) % 3);

        uint32_t ab = sbase + (kt % 3)*PS;
        uint32_t bbuf = ab + PSA;

        uint32_t afA[4][4], afB[4][4], bqA[2][4], bqB[2][4];
        ldfragsA(ab, 0, afA);  ldfragsB(bbuf, 0, bqA);
        ldfragsA(ab, 2, afB);  ldfragsB(bbuf, 2, bqB);
        mma_step(afA, bqA);
        mma_step(afB, bqB);
        ldfragsA(ab, 4, afA);  ldfragsB(bbuf, 4, bqA);
        ldfragsA(ab, 6, afB);  ldfragsB(bbuf, 6, bqB);
        mma_step(afA, bqA);
        mma_step(afB, bqB);
    }
    __syncthreads();

    // epilogue buffers: hbuf [128][132] floats (67584 B), wT [128][32] floats (16384 B)
    float* hbuf = (float*)dsm;
    float* wT = (float*)(dsm + 67840);

    for (int l = t; l < REDv*Gv; l += 256) {
        int j = l >> 5, g = l & 31;
        wT[l] = conv2_w[g*REDv + j];
    }

#pragma unroll
    for (int mi = 0; mi < 4; mi++) {
#pragma unroll
        for (int ni = 0; ni < 4; ni++) {
            int c0 = wn*32 + ni*8 + t4*2;
#pragma unroll
            for (int half = 0; half < 2; half++) {
                int c = c0 + half;
                float sc = bn_g[c] * rsqrtf(bn_v[c] + 1e-5f);
                float sh = bn_b[c] - bn_m[c]*sc;
                int rr = wm*64 + mi*16 + g8;
                hbuf[rr*132 + c]     = fmaxf(acc[mi][ni][half]     * sc + sh, 0.f);
                hbuf[(rr+8)*132 + c] = fmaxf(acc[mi][ni][2 + half] * sc + sh, 0.f);
            }
        }
    }
    __syncthreads();

    // gate[r,g] = conv2_b[g] + sum_j h[r][j]*wT[j][g]  (float4 hbuf reads)
    {
        int g = t & 31;
        int rbase = t >> 5;
        float s[16];
        float cb2 = conv2_b[g];
#pragma unroll
        for (int i = 0; i < 16; i++) s[i] = cb2;
#pragma unroll 4
        for (int j4 = 0; j4 < REDv/4; j4++) {
            float wv0 = wT[(j4*4+0)*32 + g];
            float wv1 = wT[(j4*4+1)*32 + g];
            float wv2 = wT[(j4*4+2)*32 + g];
            float wv3 = wT[(j4*4+3)*32 + g];
#pragma unroll
            for (int i = 0; i < 16; i++) {
                int r = rbase + i*8;
                float4 h4 = *(const float4*)(hbuf + r*132 + j4*4);
                s[i] += h4.x*wv0 + h4.y*wv1 + h4.z*wv2 + h4.w*wv3;
            }
        }
#pragma unroll
        for (int i = 0; i < 16; i++) {
            int r = rbase + i*8;
            g_gate[((size_t)(row0 + r))*Gv + g] = s[i];
        }
    }

    // folded Wb build: 2048 float4 per block (grid 256)
#pragma unroll
    for (int i = 0; i < 8; i++) {
        int idx = blockIdx.x*2048 + i*256 + t;
        int b = idx >> 16;
        float at0 = g_att[b*4+0], at1 = g_att[b*4+1], at2 = g_att[b*4+2], at3 = g_att[b*4+3];
        int r = idx & 65535;
        const float4* w4 = (const float4*)dyn_w;
        float4 v0 = w4[0*65536 + r], v1 = w4[1*65536 + r], v2 = w4[2*65536 + r], v3 = w4[3*65536 + r];
        float ox = at0*v0.x + at1*v1.x + at2*v2.x + at3*v3.x;
        float oy = at0*v0.y + at1*v1.y + at2*v2.y + at3*v3.y;
        float oz = at0*v0.z + at1*v1.z + at2*v2.z + at3*v3.z;
        float ow = at0*v0.w + at1*v1.w + at2*v2.w + at3*v3.w;
        ((__half2*)g_Wbh)[idx*2]   = __floats2half2_rn(ox, oy);
        ((__half2*)g_Wbh)[idx*2+1] = __floats2half2_rn(oz, ow);
    }
}

// ---------------- 4) k_gemm: out2 = x @ Wb[b]^T, fused epilogue (fp16 x in epilogue) ----------------
// BM=128, BN=128, BK=64 (8 K-tiles). 3-stage cp.async ring, lookahead 2. Grid (4, 256).
__global__ __launch_bounds__(256, 2) void k_gemm(float* __restrict__ out) {
    extern __shared__ __align__(16) unsigned char dsm[];
    uint32_t sbase = (smem_u32(dsm) + 127u) & ~127u;
    const uint32_t PSA = 128*RS64*2;              // 18432 B
    const uint32_t PS  = 2*PSA;                   // 36864 B

    int col0 = blockIdx.x * 128;
    int row0 = blockIdx.y * 128;
    int b = row0 >> 12;
    const __half* Bp = g_Wbh + (size_t)b*Dv*Dv;

    int t = threadIdx.x, warp = t >> 5, lane = t & 31;
    int g8 = lane >> 2, t4 = lane & 3;
    int wm = warp >> 2, wn = warp & 3;

    float acc[4][4][4];
#pragma unroll
    for (int mi = 0; mi < 4; mi++)
#pragma unroll
        for (int ni = 0; ni < 4; ni++)
#pragma unroll
            for (int q = 0; q < 4; q++) acc[mi][ni][q] = 0.f;

    auto issue = [&](int kt, int s) {
        uint32_t ab = sbase + s*PS;
        uint32_t bbuf = ab + PSA;
        int k0 = kt * 64;
#pragma unroll
        for (int i = 0; i < 4; i++) {
            int lin = t + i*256, r = lin >> 3, ch = lin & 7;
            uint32_t off = (uint32_t)(r*144 + ch*16);
            cp16s(ab   + off, g_xh + ((size_t)(row0 + r))*Dv + k0 + ch*8);
            cp16s(bbuf + off, Bp   + ((size_t)(col0 + r))*Dv + k0 + ch*8);
        }
        cp_commit();
    };

    auto ldfragsA = [&](uint32_t ab, int cb, uint32_t af[4][4]) {
#pragma unroll
        for (int mi = 0; mi < 4; mi++) {
            int rm = wm*64 + mi*16;
            int row = rm + ((lane>>3)&1)*8 + (lane&7);
            int gr  = cb + (lane>>4);
            ldm4(af[mi], ab + (uint32_t)(row*144 + gr*16));
        }
    };
    auto ldfragsB = [&](uint32_t bbuf, int cb, uint32_t bq[2][4]) {
#pragma unroll
        for (int p = 0; p < 2; p++) {
            int cn = wn*32 + p*16;
            int row = cn + (lane>>4)*8 + (lane&7);
            int gr  = cb + ((lane>>3)&1);
            ldm4(bq[p], bbuf + (uint32_t)(row*144 + gr*16));
        }
    };

    auto mma_step = [&](uint32_t af[4][4], uint32_t bq[2][4]) {
#pragma unroll
        for (int mi = 0; mi < 4; mi++)
#pragma unroll
            for (int ni = 0; ni < 4; ni++) {
                uint32_t bf[2] = { bq[ni>>1][(ni&1)*2], bq[ni>>1][(ni&1)*2+1] };
                mma_f16(acc[mi][ni], af[mi], bf);
            }
    };

    issue(0, 0); issue(1, 1);
    for (int kt = 0; kt < 8; kt++) {
        if (kt < 7) cp_wait<1>(); else cp_wait<0>();
        __syncthreads();
        if (kt + 2 < 8) issue(kt + 2, (kt + 2) % 3);   // never aliases kt%3

        uint32_t ab = sbase + (kt % 3)*PS;
        uint32_t bbuf = ab + PSA;

        uint32_t afA[4][4], afB[4][4], bqA[2][4], bqB[2][4];
        ldfragsA(ab, 0, afA);  ldfragsB(bbuf, 0, bqA);
        ldfragsA(ab, 2, afB);  ldfragsB(bbuf, 2, bqB);
        mma_step(afA, bqA);
        mma_step(afB, bqB);
        ldfragsA(ab, 4, afA);  ldfragsB(bbuf, 4, bqA);
        ldfragsA(ab, 6, afB);  ldfragsB(bbuf, 6, bqB);
        mma_step(afA, bqA);
        mma_step(afB, bqB);
    }

    // epilogue: y = acc + bb[b,c] + x*gate  (x read as fp16 from g_xh, L2-hot)
#pragma unroll
    for (int mi = 0; mi < 4; mi++) {
        int R0 = row0 + wm*64 + mi*16 + g8;
#pragma unroll
        for (int ni = 0; ni < 4; ni++) {
            int c = col0 + wn*32 + ni*8 + t4*2;
            float bb0 = g_bb[b*Dv + c], bb1 = g_bb[b*Dv + c + 1];
            int grp = c >> 4;

            float gv0 = g_gate[((size_t)R0)*Gv + grp];
            float2 xv0 = __half22float2(*(const __half2*)(g_xh + ((size_t)R0)*Dv + c));
            float2 y0;
            y0.x = acc[mi][ni][0] + bb0 + xv0.x*gv0;
            y0.y = acc[mi][ni][1] + bb1 + xv0.y*gv0;
            *(float2*)(out + ((size_t)R0)*Dv + c) = y0;

            int R1 = R0 + 8;
            float gv1 = g_gate[((size_t)R1)*Gv + grp];
            float2 xv1 = __half22float2(*(const __half2*)(g_xh + ((size_t)R1)*Dv + c));
            float2 y1;
            y1.x = acc[mi][ni][2] + bb0 + xv1.x*gv1;
            y1.y = acc[mi][ni][3] + bb1 + xv1.y*gv1;
            *(float2*)(out + ((size_t)R1)*Dv + c) = y1;
        }
    }
}

// ---------------- 5) LayerNorm + residual (in place on d_out; x residual stays fp32) ----------------
__global__ void k_ln(const float* __restrict__ x, const float* __restrict__ ln_g,
                     const float* __restrict__ ln_b, float* __restrict__ out) {
    int warp = threadIdx.x >> 5, lane = threadIdx.x & 31;
    int R = blockIdx.x*8 + warp;               // grid 4096, block 256
    const float4* y4 = (const float4*)(out + (size_t)R*Dv);
    float4 v[4];
    float s = 0.f, s2 = 0.f;
#pragma unroll
    for (int i = 0; i < 4; i++) {
        v[i] = y4[lane + 32*i];
        s  += v[i].x + v[i].y + v[i].z + v[i].w;
        s2 += v[i].x*v[i].x + v[i].y*v[i].y + v[i].z*v[i].z + v[i].w*v[i].w;
    }
#pragma unroll
    for (int o = 16; o > 0; o >>= 1) {
        s  += __shfl_xor_sync(0xFFFFFFFFu, s, o);
        s2 += __shfl_xor_sync(0xFFFFFFFFu, s2, o);
    }
    float mu = s * (1.f/Dv);
    float var = s2 * (1.f/Dv) - mu*mu;
    float rs = rsqrtf(var + 1e-5f);

    const float4* x4 = (const float4*)(x + (size_t)R*Dv);
    const float4* g4 = (const float4*)ln_g;
    const float4* b4 = (const float4*)ln_b;
    float4* o4 = (float4*)(out + (size_t)R*Dv);
#pragma unroll
    for (int i = 0; i < 4; i++) {
        int j = lane + 32*i;
        float4 g = g4[j], bb = b4[j], xx = x4[j];
        float4 o;
        o.x = (v[i].x - mu)*rs*g.x + bb.x + xx.x;
        o.y = (v[i].y - mu)*rs*g.y + bb.y + xx.y;
        o.z = (v[i].z - mu)*rs*g.z + bb.z + xx.z;
        o.w = (v[i].w - mu)*rs*g.w + bb.w + xx.w;
        o4[j] = o;
    }
}

// ---------------- launch ----------------
extern "C" void kernel_launch(void* const* d_in, const int* in_sizes, int n_in,
                              void* d_out, int out_size) {
    const float* x       = (const float*)d_in[0];
    const float* conv1_w = (const float*)d_in[1];
    const float* bn_g    = (const float*)d_in[2];
    const float* bn_b    = (const float*)d_in[3];
    const float* bn_m    = (const float*)d_in[4];
    const float* bn_v    = (const float*)d_in[5];
    const float* conv2_w = (const float*)d_in[6];
    const float* conv2_b = (const float*)d_in[7];
    const float* fc1_w   = (const float*)d_in[8];
    const float* fc2_w   = (const float*)d_in[9];
    const float* fc2_b   = (const float*)d_in[10];
    const float* dyn_w   = (const float*)d_in[11];
    const float* dyn_b   = (const float*)d_in[12];
    const float* ln_g    = (const float*)d_in[13];
    const float* ln_b    = (const float*)d_in[14];
    float* out = (float*)d_out;

    const int SM_PIPE = 3*2*128*RS64*2 + 128;        // 110720 B (3 stages x 36864)
    cudaFuncSetAttribute(k_gate, cudaFuncAttributeMaxDynamicSharedMemorySize, SM_PIPE);
    cudaFuncSetAttribute(k_gemm, cudaFuncAttributeMaxDynamicSharedMemorySize, SM_PIPE);

    k_pre <<<dim3(Bv, 32), 512>>>(x, conv1_w);
    k_fc1 <<<17, 256>>>(fc1_w);
    k_att2<<<1, 256>>>(fc2_w, fc2_b, dyn_b);
    k_gate<<<ROWS/128, 256, SM_PIPE>>>(bn_g, bn_b, bn_m, bn_v,
                                       conv2_w, conv2_b, dyn_w);
    k_gemm<<<dim3(Dv/128, ROWS/128), 256, SM_PIPE>>>(out);
    k_ln  <<<ROWS/8, 256>>>(x, ln_g, ln_b, out);
}